// round 16
// baseline (speedup 1.0000x reference)
#include <cuda_runtime.h>
#include <cuda_fp16.h>
#include <stdint.h>

// Problem constants: B=8, CK=64, H=W=64 -> HW=4096
#define BATCH 8
#define CKDIM 64
#define HW    4096
#define NGROUPS 256           // (b, n_tile) groups: 8 * 32
#define GROUP_SIG 16          // pair-signals per group (32 m-tiles = 16 pairs)
#define NPAIRS 2048           // CTA c handles pairs c and c+2048

// log2(e) folded into Qk's pre-converted scale so exp(a) == exp2(d)
#define BSCALE (0.125f * 1.4426950408889634f)

// SMEM: double pair buffers (A1,A2,B x 16KB each) + two fp16 E bufs + RED
#define BUF0   0
#define BUF1   49152
#define E0_OFF 98304
#define E1_OFF 131072
#define RED_OFF 163840        // 512 floats
#define SMEM_BYTES 165888

// Pre-converted fp16 inputs, K-major rows: [b][row][c] (row = m for Mk, n for Qk)
__device__ __half g_Mk16[BATCH * HW * CKDIM];
__device__ __half g_Qk16[BATCH * HW * CKDIM];   // scaled by BSCALE
__device__ float g_sums[BATCH * HW];
__device__ unsigned g_cnt[NGROUPS];

__global__ void init_kernel() {
    int i = blockIdx.x * blockDim.x + threadIdx.x;
    if (i < BATCH * HW) g_sums[i] = 0.0f;
    if (i < NGROUPS) g_cnt[i] = 0u;
}

__device__ __forceinline__ uint32_t pack2h(float v0, float v1) {
    __half2 h = __floats2half2_rn(v0, v1);
    return *(uint32_t*)&h;
}

// Transpose+convert: src [b][c][row] fp32 -> dst [b][row][c] fp16 (*scale).
// Block handles (arr, b, 64-row block); smem-staged for coalescing both sides.
__global__ __launch_bounds__(256)
void preconvert_kernel(const float* __restrict__ Mk, const float* __restrict__ Qk) {
    __shared__ float st[64 * 72];
    const int z = blockIdx.x;
    const int arr = z >> 9;               // 0 = Mk, 1 = Qk
    const int blk = z & 511;
    const int b = blk >> 6;
    const int r0 = (blk & 63) * 64;
    const float* src = (arr ? Qk : Mk) + (size_t)b * CKDIM * HW;
    __half* dst = (arr ? g_Qk16 : g_Mk16) + ((size_t)b * HW + r0) * CKDIM;
    const float scale = arr ? BSCALE : 1.0f;
    const int tid = threadIdx.x;

#pragma unroll
    for (int i = 0; i < 16; i++) {
        int idx = tid + i * 256;          // 64c x 64rows
        int c = idx >> 6, rl = idx & 63;
        st[rl * 72 + c] = src[(size_t)c * HW + r0 + rl] * scale;
    }
    __syncthreads();
#pragma unroll
    for (int i = 0; i < 2; i++) {
        int j = tid + i * 256;            // 512 x 16B chunks
        int rl = j >> 3, cb = j & 7;
        const float* p = &st[rl * 72 + cb * 8];
        uint4 w;
        w.x = pack2h(p[0], p[1]); w.y = pack2h(p[2], p[3]);
        w.z = pack2h(p[4], p[5]); w.w = pack2h(p[6], p[7]);
        *(uint4*)(dst + (size_t)rl * CKDIM + cb * 8) = w;
    }
}

// ---------------- main kernel helpers ----------------
__device__ __forceinline__ uint32_t smem_u32(const void* p) {
    uint32_t a;
    asm("{ .reg .u64 t; cvta.to.shared.u64 t, %1; cvt.u32.u64 %0, t; }"
        : "=r"(a) : "l"(p));
    return a;
}
__device__ __forceinline__ uint32_t swz(uint32_t off) {
    return off ^ ((off >> 3) & 0x70);
}
__device__ __forceinline__ float ex2(float x) {
    float r;
    asm("ex2.approx.f32 %0, %1;" : "=f"(r) : "f"(x));
    return r;
}
__device__ __forceinline__ void cp16(uint32_t dst, const void* src) {
    asm volatile("cp.async.cg.shared.global [%0], [%1], 16;"
                 :: "r"(dst), "l"(src));
}
__device__ __forceinline__ void cp_commit() {
    asm volatile("cp.async.commit_group;" ::: "memory");
}
template <int N>
__device__ __forceinline__ void cp_wait() {
    asm volatile("cp.async.wait_group %0;" :: "n"(N) : "memory");
}
__device__ __forceinline__ void sts128(uint32_t addr, uint32_t r0, uint32_t r1,
                                       uint32_t r2, uint32_t r3) {
    asm volatile("st.shared.v4.b32 [%0], {%1,%2,%3,%4};"
                 :: "r"(addr), "r"(r0), "r"(r1), "r"(r2), "r"(r3));
}
__device__ __forceinline__ void lds128(uint32_t addr, uint32_t* r) {
    asm volatile("ld.shared.v4.b32 {%0,%1,%2,%3}, [%4];"
                 : "=r"(r[0]), "=r"(r[1]), "=r"(r[2]), "=r"(r[3]) : "r"(addr));
}
__device__ __forceinline__ void ldsm4(uint32_t addr, uint32_t* r) {
    asm volatile("ldmatrix.sync.aligned.m8n8.x4.shared.b16 {%0,%1,%2,%3}, [%4];"
                 : "=r"(r[0]), "=r"(r[1]), "=r"(r[2]), "=r"(r[3]) : "r"(addr));
}
__device__ __forceinline__ void mma16816(float* d, const uint32_t* a, const uint32_t* b) {
    asm volatile(
        "mma.sync.aligned.m16n8k16.row.col.f32.f16.f16.f32 "
        "{%0,%1,%2,%3}, {%4,%5,%6,%7}, {%8,%9}, {%0,%1,%2,%3};"
        : "+f"(d[0]), "+f"(d[1]), "+f"(d[2]), "+f"(d[3])
        : "r"(a[0]), "r"(a[1]), "r"(a[2]), "r"(a[3]), "r"(b[0]), "r"(b[1]));
}
__device__ __forceinline__ void signal_grp(unsigned* cnt) {
    asm volatile("red.release.gpu.global.add.u32 [%0], %1;"
                 :: "l"(cnt), "r"(1u) : "memory");
}
__device__ __forceinline__ void wait_grp(unsigned* cnt) {
    unsigned v;
    do {
        asm volatile("ld.acquire.gpu.global.u32 %0, [%1];"
                     : "=r"(v) : "l"(cnt) : "memory");
        if (v < GROUP_SIG) __nanosleep(64);
    } while (v < GROUP_SIG);
}

// Async-load one 128x64 fp16 tile: contiguous global rows -> swizzled smem.
__device__ __forceinline__ void cp_tile(uint32_t dst, const __half* __restrict__ src,
                                        int tid) {
#pragma unroll
    for (int i = 0; i < 2; i++) {
        int chunk = tid + i * 512;        // 1024 x 16B
        int r = chunk >> 3, kb = chunk & 7;
        cp16(dst + swz((uint32_t)(r * 128 + kb * 16)), src + r * CKDIM + kb * 8);
    }
}
// Pair = A tiles (rows mp*256 .. +255 of Mk16) + B tile (rows n0..n0+127 of Qk16).
__device__ __forceinline__ void cp_pair(uint32_t buf, unsigned pr, int tid) {
    const int g = (int)(pr >> 4), mp = (int)(pr & 15u);
    const __half* Ap = g_Mk16 + ((size_t)(g >> 5) * HW + mp * 256) * CKDIM;
    const __half* Bp = g_Qk16 + ((size_t)(g >> 5) * HW + (g & 31) * 128) * CKDIM;
    cp_tile(buf, Ap, tid);
    cp_tile(buf + 16384, Ap + 128 * CKDIM, tid);
    cp_tile(buf + 32768, Bp, tid);
    cp_commit();
}

// Interleaved pair mainloop: B fragments loaded once per ks, feed both A tiles.
__device__ __forceinline__ void mma_pair(uint32_t buf, float a1[2][4][4],
                                         float a2[2][4][4], int wm, int wn, int lane) {
    const int a_row = wm * 32 + (lane & 7) + ((lane >> 3) & 1) * 8;
    const int a_kb  = (lane >> 4) * 16;
    const int b_row = wn * 32 + (lane & 7) + (lane >> 4) * 8;
    const int b_kb  = ((lane >> 3) & 1) * 16;
#pragma unroll
    for (int ks = 0; ks < 4; ks++) {
        const int kbase = ks * 32;
        uint32_t bf[8], ah1[2][4], ah2[2][4];
        ldsm4(buf + 32768 + swz((uint32_t)(b_row * 128 + kbase + b_kb)), &bf[0]);
        ldsm4(buf + 32768 + swz((uint32_t)((b_row + 16) * 128 + kbase + b_kb)), &bf[4]);
        ldsm4(buf + swz((uint32_t)(a_row * 128 + kbase + a_kb)), ah1[0]);
        ldsm4(buf + swz((uint32_t)((a_row + 16) * 128 + kbase + a_kb)), ah1[1]);
        ldsm4(buf + 16384 + swz((uint32_t)(a_row * 128 + kbase + a_kb)), ah2[0]);
        ldsm4(buf + 16384 + swz((uint32_t)((a_row + 16) * 128 + kbase + a_kb)), ah2[1]);
#pragma unroll
        for (int mi = 0; mi < 2; mi++)
#pragma unroll
            for (int ni = 0; ni < 4; ni++) {
                mma16816(a1[mi][ni], ah1[mi], &bf[ni * 2]);
                mma16816(a2[mi][ni], ah2[mi], &bf[ni * 2]);
            }
    }
}

// exp2 both accs, combined column sums, optional fp16 E park, non-atomic RED.
__device__ __forceinline__ void exp_pair(uint32_t sb, float a1[2][4][4],
                                         float a2[2][4][4], int tid, int lane,
                                         int wm, int wn, bool write_e) {
    float cs[8];
#pragma unroll
    for (int q = 0; q < 8; q++) cs[q] = 0.0f;
#pragma unroll
    for (int mi = 0; mi < 2; mi++)
#pragma unroll
        for (int ni = 0; ni < 4; ni++) {
#pragma unroll
            for (int q = 0; q < 4; q++) {
                a1[mi][ni][q] = ex2(a1[mi][ni][q]);
                a2[mi][ni][q] = ex2(a2[mi][ni][q]);
            }
            cs[2 * ni]     += a1[mi][ni][0] + a1[mi][ni][2] + a2[mi][ni][0] + a2[mi][ni][2];
            cs[2 * ni + 1] += a1[mi][ni][1] + a1[mi][ni][3] + a2[mi][ni][1] + a2[mi][ni][3];
        }
    if (write_e) {
#pragma unroll
        for (int ni = 0; ni < 4; ni++) {
            uint32_t w[4];
#pragma unroll
            for (int q = 0; q < 4; q++) w[q] = pack2h(a1[0][ni][q], a1[1][ni][q]);
            sts128(sb + E0_OFF + (uint32_t)((ni * 512 + tid) * 16), w[0], w[1], w[2], w[3]);
#pragma unroll
            for (int q = 0; q < 4; q++) w[q] = pack2h(a2[0][ni][q], a2[1][ni][q]);
            sts128(sb + E1_OFF + (uint32_t)((ni * 512 + tid) * 16), w[0], w[1], w[2], w[3]);
        }
    }
#pragma unroll
    for (int msk = 4; msk < 32; msk <<= 1)
#pragma unroll
        for (int q = 0; q < 8; q++)
            cs[q] += __shfl_xor_sync(0xFFFFFFFFu, cs[q], msk);
    if (lane < 4) {
#pragma unroll
        for (int ni = 0; ni < 4; ni++) {
            uint32_t base = (uint32_t)(RED_OFF + (wm * 128 + wn * 32 + ni * 8 + 2 * lane) * 4);
            asm volatile("st.shared.b32 [%0], %1;" :: "r"(sb + base), "f"(cs[2 * ni]));
            asm volatile("st.shared.b32 [%0], %1;" :: "r"(sb + base + 4), "f"(cs[2 * ni + 1]));
        }
    }
}

__device__ __forceinline__ void store_from_E(uint32_t sb, uint32_t eoff,
                                             const float* rs, float* __restrict__ outb,
                                             int tid, int mrow_l, int ncl) {
#pragma unroll
    for (int ni = 0; ni < 4; ni++) {
        uint32_t w[4];
        lds128(sb + eoff + (uint32_t)((ni * 512 + tid) * 16), w);
        float e0[4], e1[4];
#pragma unroll
        for (int q = 0; q < 4; q++) {
            float2 p = __half22float2(*(__half2*)&w[q]);
            e0[q] = p.x; e1[q] = p.y;
        }
        size_t ro = (size_t)mrow_l * HW + ncl + ni * 8;
        __stcs((float2*)(outb + ro),
               make_float2(e0[0] * rs[2 * ni], e0[1] * rs[2 * ni + 1]));
        __stcs((float2*)(outb + ro + (size_t)8 * HW),
               make_float2(e0[2] * rs[2 * ni], e0[3] * rs[2 * ni + 1]));
        ro += (size_t)16 * HW;
        __stcs((float2*)(outb + ro),
               make_float2(e1[0] * rs[2 * ni], e1[1] * rs[2 * ni + 1]));
        __stcs((float2*)(outb + ro + (size_t)8 * HW),
               make_float2(e1[2] * rs[2 * ni], e1[3] * rs[2 * ni + 1]));
    }
}
__device__ __forceinline__ void store_from_regs(const float acc[2][4][4],
                                                const float* rs, float* __restrict__ outb,
                                                int mrow_l, int ncl) {
#pragma unroll
    for (int mi = 0; mi < 2; mi++)
#pragma unroll
        for (int ni = 0; ni < 4; ni++) {
            size_t ro = (size_t)(mrow_l + mi * 16) * HW + ncl + ni * 8;
            __stcs((float2*)(outb + ro),
                   make_float2(acc[mi][ni][0] * rs[2 * ni], acc[mi][ni][1] * rs[2 * ni + 1]));
            __stcs((float2*)(outb + ro + (size_t)8 * HW),
                   make_float2(acc[mi][ni][2] * rs[2 * ni], acc[mi][ni][3] * rs[2 * ni + 1]));
        }
}

// CTA c handles pairs c (group g1, -> E) and c+2048 (group g2, -> regs).
// All loads issued up-front via cp.async into double buffers; waits deferred.
__global__ __launch_bounds__(512, 1)
void gemm_softmax_fused(float* __restrict__ out) {
    extern __shared__ char smem[];
    const uint32_t sb = smem_u32(smem);
    const int tid = threadIdx.x, lane = tid & 31, wid = tid >> 5;
    const int wm = wid >> 2, wn = wid & 3;
    float* RED = (float*)(smem + RED_OFF);

    const unsigned c = blockIdx.x, p2 = c + NPAIRS;
    const int g1 = (int)(c >> 4),  mp1 = (int)(c & 15u);
    const int g2 = (int)(p2 >> 4), mp2 = (int)(p2 & 15u);
    const int n1 = (g1 & 31) * 128, b1 = g1 >> 5;
    const int n2 = (g2 & 31) * 128, b2 = g2 >> 5;
    float* gs1 = &g_sums[b1 * HW + n1];
    float* gs2 = &g_sums[b2 * HW + n2];

    // both pairs' loads in flight immediately
    cp_pair(sb + BUF0, c, tid);
    cp_pair(sb + BUF1, p2, tid);

    float acc1[2][4][4], acc2[2][4][4];
#pragma unroll
    for (int i = 0; i < 2; i++)
#pragma unroll
        for (int j = 0; j < 4; j++)
#pragma unroll
            for (int q = 0; q < 4; q++) { acc1[i][j][q] = 0.f; acc2[i][j][q] = 0.f; }

    // ---- pair 1 ----
    cp_wait<1>();
    __syncthreads();
    mma_pair(sb + BUF0, acc1, acc2, wm, wn, lane);
    exp_pair(sb, acc1, acc2, tid, lane, wm, wn, true);
    __syncthreads();                      // E + RED complete
    if (tid < 128)
        atomicAdd(&gs1[tid], RED[tid] + RED[128 + tid] + RED[256 + tid] + RED[384 + tid]);
    __syncthreads();                      // gs1 atomics issued; RED reusable
    if (tid == 0) signal_grp(&g_cnt[g1]);

    // ---- pair 2 ----
    cp_wait<0>();
    __syncthreads();
#pragma unroll
    for (int i = 0; i < 2; i++)
#pragma unroll
        for (int j = 0; j < 4; j++)
#pragma unroll
            for (int q = 0; q < 4; q++) { acc1[i][j][q] = 0.f; acc2[i][j][q] = 0.f; }
    mma_pair(sb + BUF1, acc1, acc2, wm, wn, lane);
    exp_pair(sb, acc1, acc2, tid, lane, wm, wn, false);
    __syncthreads();
    if (tid < 128)
        atomicAdd(&gs2[tid], RED[tid] + RED[128 + tid] + RED[256 + tid] + RED[384 + tid]);
    __syncthreads();
    if (tid == 0) signal_grp(&g_cnt[g2]);

    const int mrow_l = wm * 32 + (lane >> 2);
    const int ncl    = wn * 32 + 2 * (lane & 3);

    // ---- store pair 1 from E ----
    if (tid == 0) wait_grp(&g_cnt[g1]);
    __syncthreads();
    {
        float rs[8];
#pragma unroll
        for (int ni = 0; ni < 4; ni++) {
            rs[2 * ni]     = __fdividef(1.0f, __ldcg(&gs1[ncl + ni * 8]));
            rs[2 * ni + 1] = __fdividef(1.0f, __ldcg(&gs1[ncl + ni * 8 + 1]));
        }
        float* outb = out + (size_t)(b1 * HW + mp1 * 256) * HW + n1;
        store_from_E(sb, E0_OFF, rs, outb, tid, mrow_l, ncl);
        store_from_E(sb, E1_OFF, rs, outb + (size_t)128 * HW, tid, mrow_l, ncl);
    }

    // ---- store pair 2 from registers ----
    if (tid == 0) wait_grp(&g_cnt[g2]);
    __syncthreads();
    {
        float rs[8];
#pragma unroll
        for (int ni = 0; ni < 4; ni++) {
            rs[2 * ni]     = __fdividef(1.0f, __ldcg(&gs2[ncl + ni * 8]));
            rs[2 * ni + 1] = __fdividef(1.0f, __ldcg(&gs2[ncl + ni * 8 + 1]));
        }
        float* outb = out + (size_t)(b2 * HW + mp2 * 256) * HW + n2;
        store_from_regs(acc1, rs, outb, mrow_l, ncl);
        store_from_regs(acc2, rs, outb + (size_t)128 * HW, mrow_l, ncl);
    }
}

extern "C" void kernel_launch(void* const* d_in, const int* in_sizes, int n_in,
                              void* d_out, int out_size) {
    const float* Mk = (const float*)d_in[0];
    const float* Qk = (const float*)d_in[1];
    float* out = (float*)d_out;

    cudaFuncSetAttribute(gemm_softmax_fused,
                         cudaFuncAttributeMaxDynamicSharedMemorySize, SMEM_BYTES);

    preconvert_kernel<<<1024, 256>>>(Mk, Qk);
    init_kernel<<<(BATCH * HW + 255) / 256, 256>>>();

    gemm_softmax_fused<<<NPAIRS, 512, SMEM_BYTES>>>(out);
}